// round 10
// baseline (speedup 1.0000x reference)
#include <cuda_runtime.h>
#include <cuda_fp16.h>
#include <math.h>

// Problem constants
#define B_  64
#define IC_ 2048
#define ID_ 16
#define K_  1024           // NC*CD = 64*16

// ---------------- device scratch (no allocations allowed) ------------------
__device__ __half g_uhat[(size_t)B_ * IC_ * K_]; // 256 MB  [b][i][k], fp16
__device__ float  g_s[3][B_ * K_];               // s per routing iteration
__device__ float  g_v0[B_ * K_];
__device__ float  g_v1[B_ * K_];

// ---------------- f32x2 packed helpers (Blackwell) -------------------------
__device__ __forceinline__ unsigned long long pack2(float lo, float hi) {
    unsigned long long r;
    asm("mov.b64 %0, {%1, %2};" : "=l"(r) : "f"(lo), "f"(hi));
    return r;
}
__device__ __forceinline__ unsigned long long fma2(unsigned long long a,
                                                   unsigned long long b,
                                                   unsigned long long c) {
    unsigned long long d;
    asm("fma.rn.f32x2 %0, %1, %2, %3;" : "=l"(d) : "l"(a), "l"(b), "l"(c));
    return d;
}
__device__ __forceinline__ unsigned long long add2(unsigned long long a,
                                                   unsigned long long b) {
    unsigned long long d;
    asm("add.rn.f32x2 %0, %1, %2;" : "=l"(d) : "l"(a), "l"(b));
    return d;
}
__device__ __forceinline__ void unpack2(unsigned long long v, float& lo, float& hi) {
    asm("mov.b64 {%0, %1}, %2;" : "=f"(lo), "=f"(hi) : "l"(v));
}

// ---------------- kernel 0: s[0..2] <- bias broadcast ----------------------
__global__ __launch_bounds__(1024) void k_init(const float* __restrict__ bias) {
    const int blk = blockIdx.x;                    // 192 blocks: 3 bufs x 64 b
    g_s[blk >> 6][(blk & 63) * K_ + threadIdx.x] = bias[threadIdx.x];
}

// ---------------- kernel 1: projection + fused iter-0 mean (R4 version) ----
#define KC    512
#define BG    32
#define ISEG  32
__global__ __launch_bounds__(256, 2) void k_project(const float* __restrict__ x,
                                                    const float* __restrict__ W) {
    const int t     = threadIdx.x;
    const int kbase = blockIdx.x * KC;
    const int bbase = blockIdx.y * BG;
    const int i0    = blockIdx.z * ISEG;
    const int k2    = kbase + 2 * t;

    __shared__ float xs[BG][16][ID_];              // 32 KB, reused per half

    unsigned long long acc[BG];
    #pragma unroll
    for (int b = 0; b < BG; b++) acc[b] = 0ull;

    for (int half = 0; half < 2; half++) {
        __syncthreads();
        for (int r = t; r < 2048; r += 256) {
            const int b   = r >> 6;
            const int rem = r & 63;
            const int ii  = rem >> 2, q = rem & 3;
            const float4 v = *(const float4*)(x +
                ((size_t)(bbase + b) * IC_ + (i0 + half * 16 + ii)) * ID_ + q * 4);
            *(float4*)&xs[b][ii][q * 4] = v;
        }
        __syncthreads();

        #pragma unroll 1
        for (int ii = 0; ii < 16; ii++) {
            const int i = i0 + half * 16 + ii;
            const float* Wi = W + (size_t)i * ID_ * K_ + k2;
            unsigned long long w[16];
            #pragma unroll
            for (int j = 0; j < 16; j++)
                w[j] = *(const unsigned long long*)(Wi + (size_t)j * K_);

            #pragma unroll 4
            for (int b = 0; b < BG; b++) {
                unsigned long long a = 0ull;
                #pragma unroll
                for (int jq = 0; jq < 4; jq++) {
                    const float4 xv = *(const float4*)&xs[b][ii][jq * 4];
                    a = fma2(w[jq * 4 + 0], pack2(xv.x, xv.x), a);
                    a = fma2(w[jq * 4 + 1], pack2(xv.y, xv.y), a);
                    a = fma2(w[jq * 4 + 2], pack2(xv.z, xv.z), a);
                    a = fma2(w[jq * 4 + 3], pack2(xv.w, xv.w), a);
                }
                float lo, hi;
                unpack2(a, lo, hi);
                *(__half2*)(g_uhat +
                    ((size_t)(bbase + b) * IC_ + i) * K_ + k2) =
                    __floats2half2_rn(lo, hi);
                acc[b] = add2(acc[b], a);
            }
        }
    }

    const float sc = 1.0f / 64.0f;                 // softmax(0) weight
    #pragma unroll 4
    for (int b = 0; b < BG; b++) {
        float lo, hi;
        unpack2(acc[b], lo, hi);
        float* sp = g_s[0] + (bbase + b) * K_ + k2;
        atomicAdd(sp,     lo * sc);
        atomicAdd(sp + 1, hi * sc);
    }
}

// ---------------- kernel 2: squash(s[it]) -> v0/v1/out ---------------------
__global__ __launch_bounds__(1024) void k_squash(int it, float* __restrict__ outbuf) {
    const int b = blockIdx.x, t = threadIdx.x;
    float sv = g_s[it][b * K_ + t];
    float sq = sv * sv;
    #pragma unroll
    for (int off = 8; off >= 1; off >>= 1)
        sq += __shfl_xor_sync(0xffffffffu, sq, off, 16);
    const float tt = sq + 1e-7f;
    const float norm = sqrtf(tt);
    const float f = tt / (1.0f + tt) / norm;
    float* dst = (it == 0) ? g_v0 : (it == 1 ? g_v1 : outbuf);
    dst[b * K_ + t] = f * sv;
}

// ---------------- kernel 3: routing pass, cp.async smem pipeline -----------
// grid = (32 i-blocks of 64, 64 b), block = 128 (4 warps).
// Stage = 4 contiguous i-rows = 8 KB via cp.async.cg; 4-stage ring (32 KB).
// Commit accounting: stage s is group #s; committed = min(blk+4, 16).
// wait_group 3 is safe only for blk <= 12; for blk >= 13 we fully drain
// (wait_group 0), which completes all remaining stages (13..15).
#define RSTG 4                   // stages
#define RPS  4                   // rows per stage
__global__ __launch_bounds__(128, 4) void k_route_impl(int second) {
    const int b    = blockIdx.y;
    const int i0   = blockIdx.x * 64;
    const int t    = threadIdx.x;
    const int w    = t >> 5;
    const int lane = t & 31;

    __shared__ __align__(16) __half sm[RSTG][RPS * K_];   // 32 KB

    // v rows (same for all warps)
    float vA[16], vB[16];
    {
        const float4* vp = (const float4*)(g_v0 + b * K_);
        #pragma unroll
        for (int q = 0; q < 4; q++) {
            float4 a = vp[lane * 4 + q];
            vA[4*q] = a.x; vA[4*q+1] = a.y; vA[4*q+2] = a.z; vA[4*q+3] = a.w;
            float4 c = vp[(lane + 32) * 4 + q];
            vB[4*q] = c.x; vB[4*q+1] = c.y; vB[4*q+2] = c.z; vB[4*q+3] = c.w;
        }
        if (second) {
            const float4* vq = (const float4*)(g_v1 + b * K_);
            #pragma unroll
            for (int q = 0; q < 4; q++) {
                float4 a = vq[lane * 4 + q];
                vA[4*q] += a.x; vA[4*q+1] += a.y; vA[4*q+2] += a.z; vA[4*q+3] += a.w;
                float4 c = vq[(lane + 32) * 4 + q];
                vB[4*q] += c.x; vB[4*q+1] += c.y; vB[4*q+2] += c.z; vB[4*q+3] += c.w;
            }
        }
    }

    const char* gsrc = (const char*)(g_uhat + ((size_t)b * IC_ + i0) * K_);

    // async 8KB stage copy: 128 threads x 4 x 16B, one commit group
    auto issue_stage = [&](int slot, int blkidx) {
        unsigned int d = (unsigned int)__cvta_generic_to_shared(&sm[slot][0]);
        const char* s = gsrc + (size_t)blkidx * RPS * K_ * 2;
        #pragma unroll
        for (int j = 0; j < 4; j++) {
            const int off = (t + j * 128) * 16;
            asm volatile("cp.async.cg.shared.global [%0], [%1], 16;\n"
                         :: "r"(d + off), "l"(s + off));
        }
        asm volatile("cp.async.commit_group;\n" ::: "memory");
    };

    #pragma unroll
    for (int st = 0; st < RSTG; st++) issue_stage(st, st);

    float sA[16], sB[16];
    #pragma unroll
    for (int q = 0; q < 16; q++) { sA[q] = 0.f; sB[q] = 0.f; }

    #pragma unroll 1
    for (int blk = 0; blk < 16; blk++) {
        if (blk < 13) {
            asm volatile("cp.async.wait_group 3;\n" ::: "memory");
        } else {
            asm volatile("cp.async.wait_group 0;\n" ::: "memory");
        }
        __syncthreads();                               // stage blk ready

        const __half* row = &sm[blk & (RSTG - 1)][w * K_];
        uint4 rA0 = *(const uint4*)(row + lane * 16);
        uint4 rA1 = *(const uint4*)(row + lane * 16 + 8);
        uint4 rB0 = *(const uint4*)(row + 512 + lane * 16);
        uint4 rB1 = *(const uint4*)(row + 512 + lane * 16 + 8);

        float uA[16], uB[16];
        {
            const __half2* h; float2 f;
            h = (const __half2*)&rA0;
            #pragma unroll
            for (int q = 0; q < 4; q++) { f = __half22float2(h[q]); uA[2*q] = f.x; uA[2*q+1] = f.y; }
            h = (const __half2*)&rA1;
            #pragma unroll
            for (int q = 0; q < 4; q++) { f = __half22float2(h[q]); uA[8+2*q] = f.x; uA[8+2*q+1] = f.y; }
            h = (const __half2*)&rB0;
            #pragma unroll
            for (int q = 0; q < 4; q++) { f = __half22float2(h[q]); uB[2*q] = f.x; uB[2*q+1] = f.y; }
            h = (const __half2*)&rB1;
            #pragma unroll
            for (int q = 0; q < 4; q++) { f = __half22float2(h[q]); uB[8+2*q] = f.x; uB[8+2*q+1] = f.y; }
        }

        float a0 = 0.f, a1 = 0.f;
        #pragma unroll
        for (int q = 0; q < 16; q++) {
            a0 = fmaf(uA[q], vA[q], a0);
            a1 = fmaf(uB[q], vB[q], a1);
        }

        const float e0 = __expf(a0);
        const float e1 = __expf(a1);
        float z = e0 + e1;
        #pragma unroll
        for (int off = 16; off >= 1; off >>= 1)
            z += __shfl_xor_sync(0xffffffffu, z, off);
        const float rz = __fdividef(1.0f, z);
        const float c0 = e0 * rz, c1 = e1 * rz;

        #pragma unroll
        for (int q = 0; q < 16; q++) {
            sA[q] = fmaf(c0, uA[q], sA[q]);
            sB[q] = fmaf(c1, uB[q], sB[q]);
        }

        __syncthreads();                               // stage blk consumed
        if (blk + RSTG < 16) issue_stage(blk & (RSTG - 1), blk + RSTG);
    }

    float* sp = g_s[second ? 2 : 1] + b * K_;
    #pragma unroll
    for (int q = 0; q < 16; q++) {
        atomicAdd(sp + lane * 16 + q, sA[q]);
        atomicAdd(sp + (lane + 32) * 16 + q, sB[q]);
    }
}

// ---------------- launcher -------------------------------------------------
extern "C" void kernel_launch(void* const* d_in, const int* in_sizes, int n_in,
                              void* d_out, int out_size) {
    const float* x    = (const float*)d_in[0];   // [64,2048,16]
    const float* W    = (const float*)d_in[1];   // [2048,16,1024]
    const float* bias = (const float*)d_in[2];   // [64,16] -> 1024
    float* out = (float*)d_out;                  // [64,64,16]

    k_init<<<192, 1024>>>(bias);                         // s0,s1,s2 = bias
    k_project<<<dim3(2, 2, 64), 256>>>(x, W);            // u_hat(fp16) + s0 mean
    k_squash<<<B_, 1024>>>(0, out);                      // v0

    k_route_impl<<<dim3(32, B_), 128>>>(0);              // s1
    k_squash<<<B_, 1024>>>(1, out);                      // v1

    k_route_impl<<<dim3(32, B_), 128>>>(1);              // s2
    k_squash<<<B_, 1024>>>(2, out);                      // v2 -> out
}

// round 11
// speedup vs baseline: 1.3551x; 1.3551x over previous
#include <cuda_runtime.h>
#include <cuda_fp16.h>
#include <math.h>

// Problem constants
#define B_  64
#define IC_ 2048
#define ID_ 16
#define K_  1024           // NC*CD = 64*16

// ---------------- device scratch (no allocations allowed) ------------------
__device__ __half g_uhat[(size_t)B_ * IC_ * K_]; // 256 MB  [b][i][k], fp16
__device__ float  g_s[3][B_ * K_];               // s per routing iteration
__device__ float  g_v0[B_ * K_];
__device__ float  g_v1[B_ * K_];

// ---------------- f32x2 packed helpers (Blackwell) -------------------------
__device__ __forceinline__ unsigned long long pack2(float lo, float hi) {
    unsigned long long r;
    asm("mov.b64 %0, {%1, %2};" : "=l"(r) : "f"(lo), "f"(hi));
    return r;
}
__device__ __forceinline__ unsigned long long fma2(unsigned long long a,
                                                   unsigned long long b,
                                                   unsigned long long c) {
    unsigned long long d;
    asm("fma.rn.f32x2 %0, %1, %2, %3;" : "=l"(d) : "l"(a), "l"(b), "l"(c));
    return d;
}
__device__ __forceinline__ unsigned long long add2(unsigned long long a,
                                                   unsigned long long b) {
    unsigned long long d;
    asm("add.rn.f32x2 %0, %1, %2;" : "=l"(d) : "l"(a), "l"(b));
    return d;
}
__device__ __forceinline__ void unpack2(unsigned long long v, float& lo, float& hi) {
    asm("mov.b64 {%0, %1}, %2;" : "=f"(lo), "=f"(hi) : "l"(v));
}

// ---------------- kernel 0: s[0..2] <- bias broadcast ----------------------
__global__ __launch_bounds__(1024) void k_init(const float* __restrict__ bias) {
    const int blk = blockIdx.x;                    // 192 blocks: 3 bufs x 64 b
    g_s[blk >> 6][(blk & 63) * K_ + threadIdx.x] = bias[threadIdx.x];
}

// ---------------- kernel 1: projection + fused iter-0 mean (R4 version) ----
#define KC    512
#define BG    32
#define ISEG  32
__global__ __launch_bounds__(256, 2) void k_project(const float* __restrict__ x,
                                                    const float* __restrict__ W) {
    const int t     = threadIdx.x;
    const int kbase = blockIdx.x * KC;
    const int bbase = blockIdx.y * BG;
    const int i0    = blockIdx.z * ISEG;
    const int k2    = kbase + 2 * t;

    __shared__ float xs[BG][16][ID_];              // 32 KB, reused per half

    unsigned long long acc[BG];
    #pragma unroll
    for (int b = 0; b < BG; b++) acc[b] = 0ull;

    for (int half = 0; half < 2; half++) {
        __syncthreads();
        for (int r = t; r < 2048; r += 256) {
            const int b   = r >> 6;
            const int rem = r & 63;
            const int ii  = rem >> 2, q = rem & 3;
            const float4 v = *(const float4*)(x +
                ((size_t)(bbase + b) * IC_ + (i0 + half * 16 + ii)) * ID_ + q * 4);
            *(float4*)&xs[b][ii][q * 4] = v;
        }
        __syncthreads();

        #pragma unroll 1
        for (int ii = 0; ii < 16; ii++) {
            const int i = i0 + half * 16 + ii;
            const float* Wi = W + (size_t)i * ID_ * K_ + k2;
            unsigned long long w[16];
            #pragma unroll
            for (int j = 0; j < 16; j++)
                w[j] = *(const unsigned long long*)(Wi + (size_t)j * K_);

            #pragma unroll 4
            for (int b = 0; b < BG; b++) {
                unsigned long long a = 0ull;
                #pragma unroll
                for (int jq = 0; jq < 4; jq++) {
                    const float4 xv = *(const float4*)&xs[b][ii][jq * 4];
                    a = fma2(w[jq * 4 + 0], pack2(xv.x, xv.x), a);
                    a = fma2(w[jq * 4 + 1], pack2(xv.y, xv.y), a);
                    a = fma2(w[jq * 4 + 2], pack2(xv.z, xv.z), a);
                    a = fma2(w[jq * 4 + 3], pack2(xv.w, xv.w), a);
                }
                float lo, hi;
                unpack2(a, lo, hi);
                *(__half2*)(g_uhat +
                    ((size_t)(bbase + b) * IC_ + i) * K_ + k2) =
                    __floats2half2_rn(lo, hi);
                acc[b] = add2(acc[b], a);
            }
        }
    }

    const float sc = 1.0f / 64.0f;                 // softmax(0) weight
    #pragma unroll 4
    for (int b = 0; b < BG; b++) {
        float lo, hi;
        unpack2(acc[b], lo, hi);
        float* sp = g_s[0] + (bbase + b) * K_ + k2;
        atomicAdd(sp,     lo * sc);
        atomicAdd(sp + 1, hi * sc);
    }
}

// ---------------- kernel 2: squash(s[it]) -> v0/v1/out ---------------------
__global__ __launch_bounds__(1024) void k_squash(int it, float* __restrict__ outbuf) {
    const int b = blockIdx.x, t = threadIdx.x;
    float sv = g_s[it][b * K_ + t];
    float sq = sv * sv;
    #pragma unroll
    for (int off = 8; off >= 1; off >>= 1)
        sq += __shfl_xor_sync(0xffffffffu, sq, off, 16);
    const float tt = sq + 1e-7f;
    const float norm = sqrtf(tt);
    const float f = tt / (1.0f + tt) / norm;
    float* dst = (it == 0) ? g_v0 : (it == 1 ? g_v1 : outbuf);
    dst[b * K_ + t] = f * sv;
}

// ---------------- kernel 3: routing pass, 2-i unrolled direct LDG ----------
// grid = (16, 64 b), block = 64 (2 autonomous warps). Warp task = 64 i's,
// processed 2 per iteration: all 8 LDG.128 issued up front (front-batched,
// MLP=8 per warp, matching the fp32 kernel that sustained 5.5 TB/s), then
// convert + softmax row0, row1. Lane owns capsules n0=lane, n1=lane+32.
template <bool SECOND>
__global__ __launch_bounds__(64) void k_route() {
    const int b    = blockIdx.y;
    const int wt   = blockIdx.x * 2 + (threadIdx.x >> 5);
    const int lane = threadIdx.x & 31;
    const int i0   = wt * 64;

    float vA[16], vB[16];
    {
        const float4* vp = (const float4*)(g_v0 + b * K_);
        #pragma unroll
        for (int q = 0; q < 4; q++) {
            float4 a = vp[lane * 4 + q];
            vA[4*q] = a.x; vA[4*q+1] = a.y; vA[4*q+2] = a.z; vA[4*q+3] = a.w;
            float4 c = vp[(lane + 32) * 4 + q];
            vB[4*q] = c.x; vB[4*q+1] = c.y; vB[4*q+2] = c.z; vB[4*q+3] = c.w;
        }
        if (SECOND) {
            const float4* vq = (const float4*)(g_v1 + b * K_);
            #pragma unroll
            for (int q = 0; q < 4; q++) {
                float4 a = vq[lane * 4 + q];
                vA[4*q] += a.x; vA[4*q+1] += a.y; vA[4*q+2] += a.z; vA[4*q+3] += a.w;
                float4 c = vq[(lane + 32) * 4 + q];
                vB[4*q] += c.x; vB[4*q+1] += c.y; vB[4*q+2] += c.z; vB[4*q+3] += c.w;
            }
        }
    }

    const uint4* base = (const uint4*)(g_uhat + ((size_t)b * IC_ + i0) * K_);
    const int ROWQ = K_ / 8;                       // uint4 per i-row (fp16)

    float sA[16], sB[16];
    #pragma unroll
    for (int q = 0; q < 16; q++) { sA[q] = 0.f; sB[q] = 0.f; }

    #pragma unroll 1
    for (int ip = 0; ip < 32; ip++) {              // 2 i per iteration
        const uint4* r0 = base + (size_t)(2 * ip) * ROWQ;
        const uint4* r1 = r0 + ROWQ;
        // 8 front-batched LDG.128
        uint4 xA0 = r0[lane * 2],      xA1 = r0[lane * 2 + 1];
        uint4 xB0 = r0[64 + lane * 2], xB1 = r0[64 + lane * 2 + 1];
        uint4 yA0 = r1[lane * 2],      yA1 = r1[lane * 2 + 1];
        uint4 yB0 = r1[64 + lane * 2], yB1 = r1[64 + lane * 2 + 1];

        #pragma unroll
        for (int half = 0; half < 2; half++) {
            uint4 hA0 = half ? yA0 : xA0;
            uint4 hA1 = half ? yA1 : xA1;
            uint4 hB0 = half ? yB0 : xB0;
            uint4 hB1 = half ? yB1 : xB1;

            float uA[16], uB[16];
            {
                const __half2* h; float2 f;
                h = (const __half2*)&hA0;
                #pragma unroll
                for (int q = 0; q < 4; q++) { f = __half22float2(h[q]); uA[2*q] = f.x; uA[2*q+1] = f.y; }
                h = (const __half2*)&hA1;
                #pragma unroll
                for (int q = 0; q < 4; q++) { f = __half22float2(h[q]); uA[8+2*q] = f.x; uA[8+2*q+1] = f.y; }
                h = (const __half2*)&hB0;
                #pragma unroll
                for (int q = 0; q < 4; q++) { f = __half22float2(h[q]); uB[2*q] = f.x; uB[2*q+1] = f.y; }
                h = (const __half2*)&hB1;
                #pragma unroll
                for (int q = 0; q < 4; q++) { f = __half22float2(h[q]); uB[8+2*q] = f.x; uB[8+2*q+1] = f.y; }
            }

            float a0 = 0.f, a1 = 0.f;
            #pragma unroll
            for (int q = 0; q < 16; q++) {
                a0 = fmaf(uA[q], vA[q], a0);
                a1 = fmaf(uB[q], vB[q], a1);
            }

            const float e0 = __expf(a0);
            const float e1 = __expf(a1);
            float z = e0 + e1;
            #pragma unroll
            for (int off = 16; off >= 1; off >>= 1)
                z += __shfl_xor_sync(0xffffffffu, z, off);
            const float rz = __fdividef(1.0f, z);
            const float c0 = e0 * rz, c1 = e1 * rz;

            #pragma unroll
            for (int q = 0; q < 16; q++) {
                sA[q] = fmaf(c0, uA[q], sA[q]);
                sB[q] = fmaf(c1, uB[q], sB[q]);
            }
        }
    }

    float* sp = g_s[SECOND ? 2 : 1] + b * K_;
    #pragma unroll
    for (int q = 0; q < 16; q++) {
        atomicAdd(sp + lane * 16 + q, sA[q]);
        atomicAdd(sp + (lane + 32) * 16 + q, sB[q]);
    }
}

// ---------------- launcher -------------------------------------------------
extern "C" void kernel_launch(void* const* d_in, const int* in_sizes, int n_in,
                              void* d_out, int out_size) {
    const float* x    = (const float*)d_in[0];   // [64,2048,16]
    const float* W    = (const float*)d_in[1];   // [2048,16,1024]
    const float* bias = (const float*)d_in[2];   // [64,16] -> 1024
    float* out = (float*)d_out;                  // [64,64,16]

    k_init<<<192, 1024>>>(bias);                         // s0,s1,s2 = bias
    k_project<<<dim3(2, 2, 64), 256>>>(x, W);            // u_hat(fp16) + s0 mean
    k_squash<<<B_, 1024>>>(0, out);                      // v0

    k_route<false><<<dim3(16, B_), 64>>>();              // s1
    k_squash<<<B_, 1024>>>(1, out);                      // v1

    k_route<true><<<dim3(16, B_), 64>>>();               // s2
    k_squash<<<B_, 1024>>>(2, out);                      // v2 -> out
}